// round 1
// baseline (speedup 1.0000x reference)
#include <cuda_runtime.h>

#define VOCAB 50257
#define EMBED 128
#define BATCH 64
#define NSENT 50
#define TC 20
#define TQ 20
#define NHOPS 3

// Scratch (device globals — no allocation allowed)
__device__ float g_u[BATCH * EMBED];
__device__ float g_m[BATCH * NSENT * EMBED];
__device__ float g_c[BATCH * NSENT * EMBED];

// ---------------------------------------------------------------------------
// Kernel 1: embedding sums.
// Blocks [0, B*NSENT): memory m and context c for one (b, sentence).
// Blocks [B*NSENT, B*NSENT+B): question embedding u0.
// 128 threads = one thread per embed dim -> fully coalesced 512B row gathers.
// ---------------------------------------------------------------------------
__global__ void embed_kernel(const int* __restrict__ stories,
                             const int* __restrict__ questions,
                             const int* __restrict__ masks,
                             const float* __restrict__ WA,
                             const float* __restrict__ WB,
                             const float* __restrict__ WC,
                             const float* __restrict__ WAT,
                             const float* __restrict__ WCT) {
    int blk = blockIdx.x;
    int d = threadIdx.x;
    if (blk < BATCH * NSENT) {
        int s = blk % NSENT;
        const int* tok = stories + blk * TC;
        const int* msk = masks + blk * TC;
        int wl = 0;
#pragma unroll
        for (int t = 0; t < TC; t++) wl += (msk[t] == 0);
        int te = (wl >= 1) ? (s + 1) : 0;
        float ma = WAT[te * EMBED + d];
        float ca = WCT[te * EMBED + d];
#pragma unroll 5
        for (int t = 0; t < TC; t++) {
            int tk = tok[t];
            ma += WA[(size_t)tk * EMBED + d];
            ca += WC[(size_t)tk * EMBED + d];
        }
        g_m[(size_t)blk * EMBED + d] = ma;
        g_c[(size_t)blk * EMBED + d] = ca;
    } else {
        int b = blk - BATCH * NSENT;
        const int* q = questions + b * TQ;
        float u = 0.f;
#pragma unroll 5
        for (int t = 0; t < TQ; t++) u += WB[(size_t)q[t] * EMBED + d];
        g_u[b * EMBED + d] = u;
    }
}

// ---------------------------------------------------------------------------
// Kernel 2: 3 attention hops. One block per batch row, 128 threads.
// u lives in smem; scores via per-warp float4 dot + shfl reduce;
// softmax over 50 by warp 0; o-aggregation thread-per-dim.
// ---------------------------------------------------------------------------
__global__ void hops_kernel() {
    int b = blockIdx.x;
    int tid = threadIdx.x;
    int w = tid >> 5, lane = tid & 31;
    __shared__ float u_s[EMBED];
    __shared__ float sc[64];
    u_s[tid] = g_u[b * EMBED + tid];
    __syncthreads();
    for (int hop = 0; hop < NHOPS; hop++) {
        float4 uv = *(const float4*)&u_s[lane * 4];
        for (int n = w; n < NSENT; n += 4) {
            float4 mv = *(const float4*)&g_m[((size_t)(b * NSENT + n)) * EMBED + lane * 4];
            float p = mv.x * uv.x + mv.y * uv.y + mv.z * uv.z + mv.w * uv.w;
#pragma unroll
            for (int o = 16; o > 0; o >>= 1) p += __shfl_xor_sync(0xffffffff, p, o);
            if (lane == 0) sc[n] = p;
        }
        __syncthreads();
        if (w == 0) {
            float v0 = (lane < NSENT) ? sc[lane] : -1e30f;
            float v1 = (lane + 32 < NSENT) ? sc[lane + 32] : -1e30f;
            float mx = fmaxf(v0, v1);
#pragma unroll
            for (int o = 16; o > 0; o >>= 1) mx = fmaxf(mx, __shfl_xor_sync(0xffffffff, mx, o));
            float e0 = (lane < NSENT) ? expf(v0 - mx) : 0.f;
            float e1 = (lane + 32 < NSENT) ? expf(v1 - mx) : 0.f;
            float s = e0 + e1;
#pragma unroll
            for (int o = 16; o > 0; o >>= 1) s += __shfl_xor_sync(0xffffffff, s, o);
            float inv = 1.f / s;
            if (lane < NSENT) sc[lane] = e0 * inv;
            if (lane + 32 < NSENT) sc[lane + 32] = e1 * inv;
        }
        __syncthreads();
        float o_acc = 0.f;
#pragma unroll 5
        for (int n = 0; n < NSENT; n++)
            o_acc += g_c[((size_t)(b * NSENT + n)) * EMBED + tid] * sc[n];
        u_s[tid] += o_acc;
        __syncthreads();
    }
    g_u[b * EMBED + tid] = u_s[tid];
}

// ---------------------------------------------------------------------------
// Kernel 3: logits = u @ W_lin^T + b_lin, using packed fma.rn.f32x2 (FFMA2).
// One thread per vocab row, all 64 batches as 32 packed batch-pairs in regs.
// u staged in smem interleaved: up[j][p] = {(u[2p][2j],u[2p+1][2j]),
//                                           (u[2p][2j+1],u[2p+1][2j+1])}
// -> per (j, p): 1 LDS.128 + 2 FFMA2 (64 scalar FMA per 3 instructions).
// ---------------------------------------------------------------------------
__device__ __forceinline__ unsigned long long pack2(float a, float b) {
    unsigned long long r;
    asm("mov.b64 %0, {%1, %2};" : "=l"(r) : "f"(a), "f"(b));
    return r;
}
__device__ __forceinline__ unsigned long long fma2(unsigned long long a,
                                                   unsigned long long b,
                                                   unsigned long long c) {
    unsigned long long d;
    asm("fma.rn.f32x2 %0, %1, %2, %3;" : "=l"(d) : "l"(a), "l"(b), "l"(c));
    return d;
}
__device__ __forceinline__ void unpack2(unsigned long long v, float& lo, float& hi) {
    asm("mov.b64 {%0, %1}, %2;" : "=f"(lo), "=f"(hi) : "l"(v));
}

__global__ void __launch_bounds__(128) logits_kernel(const float* __restrict__ W,
                                                     const float* __restrict__ bias,
                                                     float* __restrict__ out) {
    __shared__ ulonglong2 up[64][32];  // [k-pair j][batch-pair p]
    for (int e = threadIdx.x; e < 64 * 32; e += blockDim.x) {
        int j = e >> 5, p = e & 31;
        float a0 = g_u[(2 * p) * EMBED + 2 * j];
        float b0 = g_u[(2 * p + 1) * EMBED + 2 * j];
        float a1 = g_u[(2 * p) * EMBED + 2 * j + 1];
        float b1 = g_u[(2 * p + 1) * EMBED + 2 * j + 1];
        ulonglong2 t;
        t.x = pack2(a0, b0);
        t.y = pack2(a1, b1);
        up[j][p] = t;
    }
    __syncthreads();

    int v = blockIdx.x * blockDim.x + threadIdx.x;
    if (v >= VOCAB) return;

    unsigned long long acc[32];
#pragma unroll
    for (int p = 0; p < 32; p++) acc[p] = 0ull;

    const float2* wrow = (const float2*)(W + (size_t)v * EMBED);
#pragma unroll 2
    for (int j = 0; j < 64; j++) {
        float2 wv = wrow[j];
        unsigned long long w0 = pack2(wv.x, wv.x);
        unsigned long long w1 = pack2(wv.y, wv.y);
#pragma unroll
        for (int p = 0; p < 32; p++) {
            ulonglong2 t = up[j][p];
            acc[p] = fma2(w0, t.x, acc[p]);
            acc[p] = fma2(w1, t.y, acc[p]);
        }
    }

    float bl = bias[v];
#pragma unroll
    for (int p = 0; p < 32; p++) {
        float lo, hi;
        unpack2(acc[p], lo, hi);
        out[(size_t)(2 * p) * VOCAB + v] = lo + bl;
        out[(size_t)(2 * p + 1) * VOCAB + v] = hi + bl;
    }
}

extern "C" void kernel_launch(void* const* d_in, const int* in_sizes, int n_in,
                              void* d_out, int out_size) {
    const int* stories = (const int*)d_in[0];
    const int* questions = (const int*)d_in[1];
    const int* masks = (const int*)d_in[2];
    const float* WA = (const float*)d_in[3];
    const float* WB = (const float*)d_in[4];
    const float* WC = (const float*)d_in[5];
    const float* WAT = (const float*)d_in[6];
    const float* WCT = (const float*)d_in[7];
    const float* Wlin = (const float*)d_in[8];
    const float* blin = (const float*)d_in[9];
    float* out = (float*)d_out;

    embed_kernel<<<BATCH * NSENT + BATCH, EMBED>>>(stories, questions, masks,
                                                   WA, WB, WC, WAT, WCT);
    hops_kernel<<<BATCH, EMBED>>>();
    logits_kernel<<<(VOCAB + 127) / 128, 128>>>(Wlin, blin, out);
}

// round 3
// speedup vs baseline: 1.1756x; 1.1756x over previous
#include <cuda_runtime.h>

#define VOCAB 50257
#define EMBED 128
#define BATCH 64
#define NSENT 50
#define TC 20
#define TQ 20
#define NHOPS 3

// Scratch (device globals — no allocation allowed)
__device__ float g_u[BATCH * EMBED];
__device__ float g_m[BATCH * NSENT * EMBED];
__device__ float g_c[BATCH * NSENT * EMBED];

// ---------------------------------------------------------------------------
// Kernel 1: embedding sums. One WARP per sentence (or per question row).
// Lane l covers dims [4l, 4l+4) via float4. Tokens broadcast via shfl,
// mask length via ballot. 40 outstanding LDG.128 per warp -> high MLP.
// ---------------------------------------------------------------------------
__global__ void __launch_bounds__(128) embed_kernel(
        const int* __restrict__ stories,
        const int* __restrict__ questions,
        const int* __restrict__ masks,
        const float* __restrict__ WA,
        const float* __restrict__ WB,
        const float* __restrict__ WC,
        const float* __restrict__ WAT,
        const float* __restrict__ WCT) {
    int gwarp = (blockIdx.x * blockDim.x + threadIdx.x) >> 5;
    int lane = threadIdx.x & 31;

    if (gwarp < BATCH * NSENT) {
        int s = gwarp % NSENT;
        int mytok = (lane < TC) ? stories[gwarp * TC + lane] : 0;
        int mymsk = (lane < TC) ? masks[gwarp * TC + lane] : 1;
        unsigned ball = __ballot_sync(0xffffffffu, (lane < TC) && (mymsk == 0));
        int te = (ball != 0u) ? (s + 1) : 0;

        float4 ma = *(const float4*)&WAT[te * EMBED + lane * 4];
        float4 ca = *(const float4*)&WCT[te * EMBED + lane * 4];
#pragma unroll
        for (int t = 0; t < TC; t++) {
            int tk = __shfl_sync(0xffffffffu, mytok, t);
            float4 a = *(const float4*)&WA[(size_t)tk * EMBED + lane * 4];
            float4 c = *(const float4*)&WC[(size_t)tk * EMBED + lane * 4];
            ma.x += a.x; ma.y += a.y; ma.z += a.z; ma.w += a.w;
            ca.x += c.x; ca.y += c.y; ca.z += c.z; ca.w += c.w;
        }
        *(float4*)&g_m[(size_t)gwarp * EMBED + lane * 4] = ma;
        *(float4*)&g_c[(size_t)gwarp * EMBED + lane * 4] = ca;
    } else if (gwarp < BATCH * NSENT + BATCH) {
        int b = gwarp - BATCH * NSENT;
        int myq = (lane < TQ) ? questions[b * TQ + lane] : 0;
        float4 u = make_float4(0.f, 0.f, 0.f, 0.f);
#pragma unroll
        for (int t = 0; t < TQ; t++) {
            int tk = __shfl_sync(0xffffffffu, myq, t);
            float4 a = *(const float4*)&WB[(size_t)tk * EMBED + lane * 4];
            u.x += a.x; u.y += a.y; u.z += a.z; u.w += a.w;
        }
        *(float4*)&g_u[b * EMBED + lane * 4] = u;
    }
}

// ---------------------------------------------------------------------------
// Kernel 2: 3 attention hops. One block per batch row, 128 threads.
// ---------------------------------------------------------------------------
__global__ void hops_kernel() {
    int b = blockIdx.x;
    int tid = threadIdx.x;
    int w = tid >> 5, lane = tid & 31;
    __shared__ float u_s[EMBED];
    __shared__ float sc[64];
    u_s[tid] = g_u[b * EMBED + tid];
    __syncthreads();
    for (int hop = 0; hop < NHOPS; hop++) {
        float4 uv = *(const float4*)&u_s[lane * 4];
        for (int n = w; n < NSENT; n += 4) {
            float4 mv = *(const float4*)&g_m[((size_t)(b * NSENT + n)) * EMBED + lane * 4];
            float p = mv.x * uv.x + mv.y * uv.y + mv.z * uv.z + mv.w * uv.w;
#pragma unroll
            for (int o = 16; o > 0; o >>= 1) p += __shfl_xor_sync(0xffffffffu, p, o);
            if (lane == 0) sc[n] = p;
        }
        __syncthreads();
        if (w == 0) {
            float v0 = (lane < NSENT) ? sc[lane] : -1e30f;
            float v1 = (lane + 32 < NSENT) ? sc[lane + 32] : -1e30f;
            float mx = fmaxf(v0, v1);
#pragma unroll
            for (int o = 16; o > 0; o >>= 1) mx = fmaxf(mx, __shfl_xor_sync(0xffffffffu, mx, o));
            float e0 = (lane < NSENT) ? expf(v0 - mx) : 0.f;
            float e1 = (lane + 32 < NSENT) ? expf(v1 - mx) : 0.f;
            float s = e0 + e1;
#pragma unroll
            for (int o = 16; o > 0; o >>= 1) s += __shfl_xor_sync(0xffffffffu, s, o);
            float inv = 1.f / s;
            if (lane < NSENT) sc[lane] = e0 * inv;
            if (lane + 32 < NSENT) sc[lane + 32] = e1 * inv;
        }
        __syncthreads();
        float o_acc = 0.f;
#pragma unroll 5
        for (int n = 0; n < NSENT; n++)
            o_acc += g_c[((size_t)(b * NSENT + n)) * EMBED + tid] * sc[n];
        u_s[tid] += o_acc;
        __syncthreads();
    }
    g_u[b * EMBED + tid] = u_s[tid];
}

// ---------------------------------------------------------------------------
// Kernel 3: logits = u @ W_lin^T + b_lin with packed fma.rn.f32x2.
// Each thread: 2 adjacent vocab rows x all 64 batches (32 packed pairs).
// Per float4 W-load pair: 2 LDS.128 feed 8 FFMA2 (1 LDS : 4 FFMA2 ratio).
// Outputs stored as scalar STG.32 — VOCAB is odd so float2 stores would be
// misaligned on odd batch rows (this trapped in round 2).
// ---------------------------------------------------------------------------
__device__ __forceinline__ unsigned long long pack2(float a, float b) {
    unsigned long long r;
    asm("mov.b64 %0, {%1, %2};" : "=l"(r) : "f"(a), "f"(b));
    return r;
}
__device__ __forceinline__ unsigned long long fma2(unsigned long long a,
                                                   unsigned long long b,
                                                   unsigned long long c) {
    unsigned long long d;
    asm("fma.rn.f32x2 %0, %1, %2, %3;" : "=l"(d) : "l"(a), "l"(b), "l"(c));
    return d;
}
__device__ __forceinline__ void unpack2(unsigned long long v, float& lo, float& hi) {
    asm("mov.b64 {%0, %1}, %2;" : "=f"(lo), "=f"(hi) : "l"(v));
}

__global__ void __launch_bounds__(128) logits_kernel(const float* __restrict__ W,
                                                     const float* __restrict__ bias,
                                                     float* __restrict__ out) {
    // up[j][p]: j = k-pair (2j, 2j+1), p = batch-pair (2p, 2p+1)
    // up[j][p].x = {u[2p][2j],   u[2p+1][2j]}
    // up[j][p].y = {u[2p][2j+1], u[2p+1][2j+1]}
    __shared__ ulonglong2 up[64][32];
    for (int e = threadIdx.x; e < 64 * 32; e += blockDim.x) {
        int j = e >> 5, p = e & 31;
        ulonglong2 t;
        t.x = pack2(g_u[(2 * p) * EMBED + 2 * j], g_u[(2 * p + 1) * EMBED + 2 * j]);
        t.y = pack2(g_u[(2 * p) * EMBED + 2 * j + 1], g_u[(2 * p + 1) * EMBED + 2 * j + 1]);
        up[j][p] = t;
    }
    __syncthreads();

    int v = blockIdx.x * blockDim.x + threadIdx.x;  // vocab pair index
    int r0 = 2 * v;
    if (r0 >= VOCAB) return;
    int r1 = 2 * v + 1;
    bool has_r1 = (r1 < VOCAB);

    unsigned long long acc0[32], acc1[32];
#pragma unroll
    for (int p = 0; p < 32; p++) { acc0[p] = 0ull; acc1[p] = 0ull; }

    const float4* w0 = (const float4*)(W + (size_t)r0 * EMBED);
    const float4* w1 = (const float4*)(W + (size_t)(has_r1 ? r1 : r0) * EMBED);

#pragma unroll 4
    for (int jq = 0; jq < 32; jq++) {  // jq covers k = 4jq .. 4jq+3 (j-pairs 2jq, 2jq+1)
        float4 a = w0[jq];
        float4 b = w1[jq];
        unsigned long long a0 = pack2(a.x, a.x), a1 = pack2(a.y, a.y);
        unsigned long long a2 = pack2(a.z, a.z), a3 = pack2(a.w, a.w);
        unsigned long long b0 = pack2(b.x, b.x), b1 = pack2(b.y, b.y);
        unsigned long long b2 = pack2(b.z, b.z), b3 = pack2(b.w, b.w);
#pragma unroll
        for (int p = 0; p < 32; p++) {
            ulonglong2 t0 = up[2 * jq][p];
            ulonglong2 t1 = up[2 * jq + 1][p];
            acc0[p] = fma2(a0, t0.x, acc0[p]);
            acc0[p] = fma2(a1, t0.y, acc0[p]);
            acc0[p] = fma2(a2, t1.x, acc0[p]);
            acc0[p] = fma2(a3, t1.y, acc0[p]);
            acc1[p] = fma2(b0, t0.x, acc1[p]);
            acc1[p] = fma2(b1, t0.y, acc1[p]);
            acc1[p] = fma2(b2, t1.x, acc1[p]);
            acc1[p] = fma2(b3, t1.y, acc1[p]);
        }
    }

    float bl0 = bias[r0];
    float bl1 = has_r1 ? bias[r1] : 0.f;
#pragma unroll
    for (int p = 0; p < 32; p++) {
        float x0, y0, x1, y1;
        unpack2(acc0[p], x0, y0);  // batches 2p, 2p+1 for row r0
        unpack2(acc1[p], x1, y1);  // batches 2p, 2p+1 for row r1
        size_t base0 = (size_t)(2 * p) * VOCAB;
        size_t base1 = (size_t)(2 * p + 1) * VOCAB;
        out[base0 + r0] = x0 + bl0;
        out[base1 + r0] = y0 + bl0;
        if (has_r1) {
            out[base0 + r1] = x1 + bl1;
            out[base1 + r1] = y1 + bl1;
        }
    }
}

extern "C" void kernel_launch(void* const* d_in, const int* in_sizes, int n_in,
                              void* d_out, int out_size) {
    const int* stories = (const int*)d_in[0];
    const int* questions = (const int*)d_in[1];
    const int* masks = (const int*)d_in[2];
    const float* WA = (const float*)d_in[3];
    const float* WB = (const float*)d_in[4];
    const float* WC = (const float*)d_in[5];
    const float* WAT = (const float*)d_in[6];
    const float* WCT = (const float*)d_in[7];
    const float* Wlin = (const float*)d_in[8];
    const float* blin = (const float*)d_in[9];
    float* out = (float*)d_out;

    // warps: BATCH*NSENT sentences + BATCH questions = 3264 -> 816 blocks x 128
    int total_warps = BATCH * NSENT + BATCH;
    int embed_blocks = (total_warps * 32 + 127) / 128;
    embed_kernel<<<embed_blocks, 128>>>(stories, questions, masks, WA, WB, WC, WAT, WCT);
    hops_kernel<<<BATCH, EMBED>>>();
    int vpairs = (VOCAB + 1) / 2;  // 25129
    logits_kernel<<<(vpairs + 127) / 128, 128>>>(Wlin, blin, out);
}